// round 15
// baseline (speedup 1.0000x reference)
#include <cuda_runtime.h>
#include <cuda_fp16.h>
#include <cstdint>
#include <math.h>

#define Bsz   8
#define CIN   512
#define COUT  512
#define HH    64
#define WW    64
#define KAREA 9
#define RED   (CIN*KAREA)

#define BK      64
#define NCHUNK  (KAREA*(CIN/BK))   // 72
#define XPAD_H  66
#define XROW    64
#define XPLANE  (XPAD_H*XROW)      // 4224

// ---------------- static device scratch --------------------------------------
__device__ float  g_S[Bsz*CIN];
__device__ float  g_S2[Bsz*CIN];
__device__ float  g_D[Bsz*COUT];
__device__ __half g_Ah[(size_t)COUT*KAREA*CIN];        // [o][k][i]
__device__ __half g_Xh[(size_t)3*Bsz*CIN*XPLANE];      // [kx][b][ci][y+1][x], pads stay 0

// ---------------- helpers ------------------------------------------------------
__device__ __forceinline__ uint32_t smem_u32(const void* p){
    uint32_t a;
    asm("{ .reg .u64 t; cvta.to.shared.u64 t, %1; cvt.u32.u64 %0, t; }" : "=r"(a) : "l"(p));
    return a;
}
__device__ __forceinline__ void cp16(uint32_t dst, const void* src){
    asm volatile("cp.async.cg.shared.global [%0], [%1], 16;" :: "r"(dst), "l"(src));
}
__device__ __forceinline__ void ldsm_x4(uint32_t* r, uint32_t addr){
    asm volatile("ldmatrix.sync.aligned.m8n8.x4.shared.b16 {%0,%1,%2,%3}, [%4];"
                 : "=r"(r[0]),"=r"(r[1]),"=r"(r[2]),"=r"(r[3]) : "r"(addr));
}
__device__ __forceinline__ void ldsm_x4t(uint32_t* r, uint32_t addr){
    asm volatile("ldmatrix.sync.aligned.m8n8.x4.trans.shared.b16 {%0,%1,%2,%3}, [%4];"
                 : "=r"(r[0]),"=r"(r[1]),"=r"(r[2]),"=r"(r[3]) : "r"(addr));
}
// fp16-accumulate HMMA: D,C are 2 b32 regs (4 halves)
__device__ __forceinline__ void mma_f16acc(uint32_t* c, const uint32_t* a, const uint32_t* b){
    asm volatile("mma.sync.aligned.m16n8k16.row.col.f16.f16.f16.f16 "
        "{%0,%1}, {%2,%3,%4,%5}, {%6,%7}, {%0,%1};"
        : "+r"(c[0]),"+r"(c[1])
        : "r"(a[0]),"r"(a[1]),"r"(a[2]),"r"(a[3]), "r"(b[0]),"r"(b[1]));
}
__device__ __forceinline__ uint32_t h2pack(__half a, __half b){
    __half2 t = __halves2half2(a, b);
    return *(uint32_t*)&t;
}

// ---------------- prep 1: style modulation (warp per output) -------------------
__global__ void k_style(const float* __restrict__ style, const float* __restrict__ mw){
    int gw   = blockIdx.x*8 + (threadIdx.x >> 5);
    int lane = threadIdx.x & 31;
    int b = gw >> 9;
    int i = gw & 511;
    const float4* row = (const float4*)(mw + (size_t)i*CIN) + lane;
    const float4* st  = (const float4*)(style + (size_t)b*CIN) + lane;
    float acc = 0.f;
#pragma unroll
    for (int j = 0; j < 4; j++){
        float4 r = row[j*32];
        float4 s = st[j*32];
        acc += r.x*s.x + r.y*s.y + r.z*s.z + r.w*s.w;
    }
#pragma unroll
    for (int off = 16; off; off >>= 1) acc += __shfl_xor_sync(~0u, acc, off);
    if (!lane){ g_S[gw] = acc; g_S2[gw] = acc*acc; }
}

// ---------------- prep 2: FUSED (weight pack + demod) | (x expand) -------------
#define PREPO_BLKS COUT                            // 512
#define PREPX_BLKS ((Bsz*CIN*HH*WW)/(8*256))       // 8192

__global__ void __launch_bounds__(256)
k_prep(const float* __restrict__ w, const float* __restrict__ x){
    const int tid = threadIdx.x;
    if (blockIdx.x < PREPO_BLKS){
        __shared__ float smw[RED];
        __shared__ float q[CIN];
        const int o = blockIdx.x;
        const float4* src = (const float4*)(w + (size_t)o*RED);
#pragma unroll
        for (int it = 0; it < RED/4/256 + 1; it++){
            int idx = tid + it*256;
            if (idx < RED/4) ((float4*)smw)[idx] = src[idx];
        }
        __syncthreads();
        __half* dst = g_Ah + (size_t)o*RED;
#pragma unroll
        for (int it = 0; it < RED/256; it++){
            int idx = tid + it*256;
            int k = idx >> 9;
            int i = idx & 511;
            dst[idx] = __float2half_rn(smw[i*KAREA + k]);
        }
#pragma unroll
        for (int it = 0; it < 2; it++){
            int i = tid + it*256;
            float s = 0.f;
#pragma unroll
            for (int k = 0; k < KAREA; k++){ float v = smw[i*KAREA + k]; s += v*v; }
            q[i] = s;
        }
        __syncthreads();
        int wb   = tid >> 5;
        int lane = tid & 31;
        const float* s2 = g_S2 + wb*CIN;
        float sum = 0.f;
#pragma unroll
        for (int j = 0; j < 16; j++){
            int i = lane + j*32;
            sum += q[i]*s2[i];
        }
#pragma unroll
        for (int off = 16; off; off >>= 1) sum += __shfl_xor_sync(~0u, sum, off);
        if (!lane)
            g_D[wb*COUT + o] = rsqrtf((float)RED) * rsqrtf(sum/(float)RED + 1e-8f);
    } else {
        int gid = (blockIdx.x - PREPO_BLKS)*256 + tid;
        int t  = gid & 7;
        int y  = (gid >> 3) & 63;
        int ci = (gid >> 9) & 511;
        int b  = gid >> 18;
        float s = g_S[b*CIN + ci];
        const float4* src = (const float4*)(x + (((size_t)(b*CIN + ci)*64 + y)<<6) + (t<<3));
        float4 f0 = src[0], f1 = src[1];
        float v0=f0.x*s, v1=f0.y*s, v2=f0.z*s, v3=f0.w*s;
        float v4=f1.x*s, v5=f1.y*s, v6=f1.z*s, v7=f1.w*s;
        __half h0=__float2half_rn(v0), h1=__float2half_rn(v1),
               h2=__float2half_rn(v2), h3=__float2half_rn(v3),
               h4=__float2half_rn(v4), h5=__float2half_rn(v5),
               h6=__float2half_rn(v6), h7=__float2half_rn(v7);
        float pl = __shfl_up_sync(~0u,  v7, 1);
        float nf = __shfl_down_sync(~0u, v0, 1);
        __half hpl = (t==0) ? __float2half_rn(0.f) : __float2half_rn(pl);
        __half hnf = (t==7) ? __float2half_rn(0.f) : __float2half_rn(nf);
        size_t rowOff = (size_t)(b*CIN + ci)*XPLANE + (size_t)(y+1)*XROW + (t<<3);
        const size_t kxStride = (size_t)Bsz*CIN*XPLANE;
        uint4 c1 = { h2pack(h0,h1), h2pack(h2,h3), h2pack(h4,h5), h2pack(h6,h7) };
        uint4 c0 = { h2pack(hpl,h0), h2pack(h1,h2), h2pack(h3,h4), h2pack(h5,h6) };
        uint4 c2 = { h2pack(h1,h2), h2pack(h3,h4), h2pack(h5,h6), h2pack(h7,hnf) };
        *(uint4*)(g_Xh + rowOff)              = c0;
        *(uint4*)(g_Xh + kxStride + rowOff)   = c1;
        *(uint4*)(g_Xh + 2*kxStride + rowOff) = c2;
    }
}

// ---------------- main mma.sync kernel ------------------------------------------
// CTA 64 couts x 128 px, 128 threads (4 warps, 1m x 4n), warp tile 64x32.
// BK=64, 2-stage cp.async, 4 CTAs/SM. fp16 chunk accumulation (testing 2x HMMA
// rate) promoted to fp32 master once per chunk.

#define APAD   72
#define BPAD   136
#define A_ST   (64*APAD*2)
#define B_ST   (BK*BPAD*2)
#define STAGE  (A_ST + B_ST)         // 26624 B
#define SMEM_SZ (2*STAGE)            // 53248 B

__global__ void __launch_bounds__(128, 4)
k_conv_mma(float* __restrict__ out)
{
    extern __shared__ __align__(16) char smraw[];
    const uint32_t s0 = smem_u32(smraw);

    const int tid  = threadIdx.x;
    const int lane = tid & 31;
    const int wn   = tid >> 5;

    const int b   = blockIdx.z;
    const int co0 = blockIdx.y << 6;
    const int y0  = blockIdx.x << 1;

    float acc[4][4][4];
#pragma unroll
    for (int mt = 0; mt < 4; mt++)
#pragma unroll
        for (int nt = 0; nt < 4; nt++)
#pragma unroll
            for (int r = 0; r < 4; r++) acc[mt][nt][r] = 0.f;

    const uint32_t aOff = (((lane & 15))*APAD + ((lane >> 4) << 3))*2;
    const int bg = lane >> 3;
    const uint32_t bOff = ((((bg & 1) << 3) + (lane & 7))*BPAD + wn*32 + ((bg >> 1) << 3))*2;

    auto load_chunk = [&](int ch, int buf){
        int sh  = ch >> 3;
        int ci0 = (ch & 7) << 6;
        int ky  = sh / 3;
        int kx  = sh - ky*3;
        const __half* aSrc = g_Ah + (size_t)co0*RED + (size_t)sh*CIN + ci0;
        const __half* xSrc = g_Xh + (((size_t)kx*Bsz + b)*CIN + ci0)*XPLANE
                           + (size_t)(y0 + ky)*XROW;
        uint32_t dA = s0 + buf*STAGE;
        uint32_t dB = dA + A_ST;
#pragma unroll
        for (int it = 0; it < 12; it++){
            int idx = tid + (it << 7);
            if (idx < 512){
                int m = idx >> 3, q = idx & 7;
                cp16(dA + m*(APAD*2) + q*16, aSrc + (size_t)m*RED + (q<<3));
            } else {
                int i2 = idx - 512;
                int k  = i2 >> 4;
                int q  = i2 & 15;
                cp16(dB + k*(BPAD*2) + q*16, xSrc + (size_t)k*XPLANE + (q<<3));
            }
        }
        asm volatile("cp.async.commit_group;");
    };

    load_chunk(0, 0);

    for (int c = 0; c < NCHUNK; c++){
        asm volatile("cp.async.wait_group 0;");
        __syncthreads();

        if (c + 1 < NCHUNK) load_chunk(c+1, (c+1) & 1);

        const uint32_t aBase = s0 + (c & 1)*STAGE;
        const uint32_t bBase = aBase + A_ST;

        // fp16 chunk accumulators (zeroed each chunk)
        uint32_t hacc[4][4][2];
#pragma unroll
        for (int mt = 0; mt < 4; mt++)
#pragma unroll
            for (int nt = 0; nt < 4; nt++){
                hacc[mt][nt][0] = 0u; hacc[mt][nt][1] = 0u;
            }

#pragma unroll
        for (int ks = 0; ks < 4; ks++){
            uint32_t afr[4][4], bfr[2][4];
#pragma unroll
            for (int mt = 0; mt < 4; mt++)
                ldsm_x4(afr[mt], aBase + aOff + (mt*16*APAD + ks*16)*2);
#pragma unroll
            for (int np = 0; np < 2; np++)
                ldsm_x4t(bfr[np], bBase + bOff + (ks*16*BPAD + np*16)*2);
#pragma unroll
            for (int mt = 0; mt < 4; mt++)
#pragma unroll
                for (int nt = 0; nt < 4; nt++)
                    mma_f16acc(hacc[mt][nt], afr[mt], &bfr[nt>>1][(nt&1)*2]);
        }

        // promote chunk sum to fp32 master
#pragma unroll
        for (int mt = 0; mt < 4; mt++)
#pragma unroll
            for (int nt = 0; nt < 4; nt++){
                float2 lo = __half22float2(*(__half2*)&hacc[mt][nt][0]);
                float2 hi = __half22float2(*(__half2*)&hacc[mt][nt][1]);
                acc[mt][nt][0] += lo.x;
                acc[mt][nt][1] += lo.y;
                acc[mt][nt][2] += hi.x;
                acc[mt][nt][3] += hi.y;
            }
    }

    // ---- epilogue ----
    const int row0 = lane >> 2;
    const int col0 = (lane & 3) << 1;
#pragma unroll
    for (int mt = 0; mt < 4; mt++){
        int cout_a = co0 + mt*16 + row0;
        int cout_b = cout_a + 8;
        float dva = g_D[b*COUT + cout_a];
        float dvb = g_D[b*COUT + cout_b];
        float* opa = out + ((size_t)(b*COUT + cout_a)*HH + y0)*WW;
        float* opb = out + ((size_t)(b*COUT + cout_b)*HH + y0)*WW;
#pragma unroll
        for (int nt = 0; nt < 4; nt++){
            int n  = wn*32 + nt*8 + col0;
            int yy = n >> 6;
            int xx = n & 63;
            float2 va, vb;
            va.x = acc[mt][nt][0]*dva; va.y = acc[mt][nt][1]*dva;
            vb.x = acc[mt][nt][2]*dvb; vb.y = acc[mt][nt][3]*dvb;
            *(float2*)(opa + (size_t)yy*WW + xx) = va;
            *(float2*)(opb + (size_t)yy*WW + xx) = vb;
        }
    }
}

// ---------------- launch --------------------------------------------------------
extern "C" void kernel_launch(void* const* d_in, const int* in_sizes, int n_in,
                              void* d_out, int out_size) {
    const float *x = nullptr, *style = nullptr, *weight = nullptr, *mod_w = nullptr;
    for (int i = 0; i < n_in; i++){
        switch (in_sizes[i]){
            case Bsz*CIN*HH*WW:   x      = (const float*)d_in[i]; break;
            case Bsz*CIN:         style  = (const float*)d_in[i]; break;
            case COUT*CIN*KAREA:  weight = (const float*)d_in[i]; break;
            case CIN*CIN:         mod_w  = (const float*)d_in[i]; break;
        }
    }
    float* out = (float*)d_out;

    cudaFuncSetAttribute(k_conv_mma, cudaFuncAttributeMaxDynamicSharedMemorySize, SMEM_SZ);

    k_style<<<(Bsz*CIN)/8, 256>>>(style, mod_w);
    k_prep<<<PREPO_BLKS + PREPX_BLKS, 256>>>(weight, x);

    dim3 grid(HH/2, COUT/64, Bsz);       // 32 x 8 x 8 = 2048 CTAs
    k_conv_mma<<<grid, 128, SMEM_SZ>>>(out);
}

// round 16
// speedup vs baseline: 1.1320x; 1.1320x over previous
#include <cuda_runtime.h>
#include <cuda_fp16.h>
#include <cstdint>
#include <math.h>

#define Bsz   8
#define CIN   512
#define COUT  512
#define HH    64
#define WW    64
#define KAREA 9
#define RED   (CIN*KAREA)

#define BK      64
#define NCHUNK  (KAREA*(CIN/BK))   // 72
#define XPAD_H  66
#define XROW    64
#define XPLANE  (XPAD_H*XROW)      // 4224

// ---------------- static device scratch --------------------------------------
__device__ float  g_S[Bsz*CIN];
__device__ float  g_S2[Bsz*CIN];
__device__ float  g_D[Bsz*COUT];
__device__ __half g_Ah[(size_t)COUT*KAREA*CIN];        // [o][k][i]
__device__ __half g_Xh[(size_t)3*Bsz*CIN*XPLANE];      // [kx][b][ci][y+1][x], pads stay 0

// ---------------- helpers ------------------------------------------------------
__device__ __forceinline__ uint32_t smem_u32(const void* p){
    uint32_t a;
    asm("{ .reg .u64 t; cvta.to.shared.u64 t, %1; cvt.u32.u64 %0, t; }" : "=r"(a) : "l"(p));
    return a;
}
__device__ __forceinline__ void cp16(uint32_t dst, const void* src){
    asm volatile("cp.async.cg.shared.global [%0], [%1], 16;" :: "r"(dst), "l"(src));
}
__device__ __forceinline__ void ldsm_x4(uint32_t* r, uint32_t addr){
    asm volatile("ldmatrix.sync.aligned.m8n8.x4.shared.b16 {%0,%1,%2,%3}, [%4];"
                 : "=r"(r[0]),"=r"(r[1]),"=r"(r[2]),"=r"(r[3]) : "r"(addr));
}
__device__ __forceinline__ void ldsm_x4t(uint32_t* r, uint32_t addr){
    asm volatile("ldmatrix.sync.aligned.m8n8.x4.trans.shared.b16 {%0,%1,%2,%3}, [%4];"
                 : "=r"(r[0]),"=r"(r[1]),"=r"(r[2]),"=r"(r[3]) : "r"(addr));
}
__device__ __forceinline__ void mma_f16(float* c, const uint32_t* a, const uint32_t* b){
    asm volatile("mma.sync.aligned.m16n8k16.row.col.f32.f16.f16.f32 "
        "{%0,%1,%2,%3}, {%4,%5,%6,%7}, {%8,%9}, {%0,%1,%2,%3};"
        : "+f"(c[0]),"+f"(c[1]),"+f"(c[2]),"+f"(c[3])
        : "r"(a[0]),"r"(a[1]),"r"(a[2]),"r"(a[3]), "r"(b[0]),"r"(b[1]));
}
__device__ __forceinline__ uint32_t h2pack(__half a, __half b){
    __half2 t = __halves2half2(a, b);
    return *(uint32_t*)&t;
}

// ---------------- prep 1: style modulation (warp per output) -------------------
__global__ void k_style(const float* __restrict__ style, const float* __restrict__ mw){
    int gw   = blockIdx.x*8 + (threadIdx.x >> 5);
    int lane = threadIdx.x & 31;
    int b = gw >> 9;
    int i = gw & 511;
    const float4* row = (const float4*)(mw + (size_t)i*CIN) + lane;
    const float4* st  = (const float4*)(style + (size_t)b*CIN) + lane;
    float acc = 0.f;
#pragma unroll
    for (int j = 0; j < 4; j++){
        float4 r = row[j*32];
        float4 s = st[j*32];
        acc += r.x*s.x + r.y*s.y + r.z*s.z + r.w*s.w;
    }
#pragma unroll
    for (int off = 16; off; off >>= 1) acc += __shfl_xor_sync(~0u, acc, off);
    if (!lane){ g_S[gw] = acc; g_S2[gw] = acc*acc; }
}

// ---------------- prep 2: FUSED (weight pack + demod) | (x expand) -------------
#define PREPO_BLKS COUT                            // 512
#define PREPX_BLKS ((Bsz*CIN*HH*WW)/(8*256))       // 8192

__global__ void __launch_bounds__(256)
k_prep(const float* __restrict__ w, const float* __restrict__ x){
    const int tid = threadIdx.x;
    if (blockIdx.x < PREPO_BLKS){
        // ---- per-cout weight pack + fused demod ----
        __shared__ float smw[RED];
        __shared__ float q[CIN];
        const int o = blockIdx.x;
        const float4* src = (const float4*)(w + (size_t)o*RED);
#pragma unroll
        for (int it = 0; it < RED/4/256 + 1; it++){
            int idx = tid + it*256;
            if (idx < RED/4) ((float4*)smw)[idx] = src[idx];
        }
        __syncthreads();
        __half* dst = g_Ah + (size_t)o*RED;
#pragma unroll
        for (int it = 0; it < RED/256; it++){
            int idx = tid + it*256;
            int k = idx >> 9;
            int i = idx & 511;
            dst[idx] = __float2half_rn(smw[i*KAREA + k]);
        }
#pragma unroll
        for (int it = 0; it < 2; it++){
            int i = tid + it*256;
            float s = 0.f;
#pragma unroll
            for (int k = 0; k < KAREA; k++){ float v = smw[i*KAREA + k]; s += v*v; }
            q[i] = s;
        }
        __syncthreads();
        int wb   = tid >> 5;
        int lane = tid & 31;
        const float* s2 = g_S2 + wb*CIN;
        float sum = 0.f;
#pragma unroll
        for (int j = 0; j < 16; j++){
            int i = lane + j*32;
            sum += q[i]*s2[i];
        }
#pragma unroll
        for (int off = 16; off; off >>= 1) sum += __shfl_xor_sync(~0u, sum, off);
        if (!lane)
            g_D[wb*COUT + o] = rsqrtf((float)RED) * rsqrtf(sum/(float)RED + 1e-8f);
    } else {
        // ---- x modulate + shift-expand (8 px/thread, aligned uint4 stores) ----
        int gid = (blockIdx.x - PREPO_BLKS)*256 + tid;
        int t  = gid & 7;
        int y  = (gid >> 3) & 63;
        int ci = (gid >> 9) & 511;
        int b  = gid >> 18;
        float s = g_S[b*CIN + ci];
        const float4* src = (const float4*)(x + (((size_t)(b*CIN + ci)*64 + y)<<6) + (t<<3));
        float4 f0 = src[0], f1 = src[1];
        float v0=f0.x*s, v1=f0.y*s, v2=f0.z*s, v3=f0.w*s;
        float v4=f1.x*s, v5=f1.y*s, v6=f1.z*s, v7=f1.w*s;
        __half h0=__float2half_rn(v0), h1=__float2half_rn(v1),
               h2=__float2half_rn(v2), h3=__float2half_rn(v3),
               h4=__float2half_rn(v4), h5=__float2half_rn(v5),
               h6=__float2half_rn(v6), h7=__float2half_rn(v7);
        float pl = __shfl_up_sync(~0u,  v7, 1);
        float nf = __shfl_down_sync(~0u, v0, 1);
        __half hpl = (t==0) ? __float2half_rn(0.f) : __float2half_rn(pl);
        __half hnf = (t==7) ? __float2half_rn(0.f) : __float2half_rn(nf);
        size_t rowOff = (size_t)(b*CIN + ci)*XPLANE + (size_t)(y+1)*XROW + (t<<3);
        const size_t kxStride = (size_t)Bsz*CIN*XPLANE;
        uint4 c1 = { h2pack(h0,h1), h2pack(h2,h3), h2pack(h4,h5), h2pack(h6,h7) };
        uint4 c0 = { h2pack(hpl,h0), h2pack(h1,h2), h2pack(h3,h4), h2pack(h5,h6) };
        uint4 c2 = { h2pack(h1,h2), h2pack(h3,h4), h2pack(h5,h6), h2pack(h7,hnf) };
        *(uint4*)(g_Xh + rowOff)              = c0;
        *(uint4*)(g_Xh + kxStride + rowOff)   = c1;
        *(uint4*)(g_Xh + 2*kxStride + rowOff) = c2;
    }
}

// ---------------- main mma.sync kernel ------------------------------------------
// CTA 64 couts x 128 px, 128 threads (4 warps, 1m x 4n), warp tile 64x32.
// BK=64, 2-stage cp.async, 4 CTAs/SM. Demod scales prefetched pre-loop.

#define APAD   72                    // halfs per A smem row (144B)
#define BPAD   136                   // halfs per B smem row (272B)
#define A_ST   (64*APAD*2)           // 9216 B
#define B_ST   (BK*BPAD*2)           // 17408 B
#define STAGE  (A_ST + B_ST)         // 26624 B
#define SMEM_SZ (2*STAGE)            // 53248 B

__global__ void __launch_bounds__(128, 4)
k_conv_mma(float* __restrict__ out)
{
    extern __shared__ __align__(16) char smraw[];
    const uint32_t s0 = smem_u32(smraw);

    const int tid  = threadIdx.x;
    const int lane = tid & 31;
    const int wn   = tid >> 5;

    const int b   = blockIdx.z;
    const int co0 = blockIdx.y << 6;
    const int y0  = blockIdx.x << 1;

    float acc[4][4][4];
#pragma unroll
    for (int mt = 0; mt < 4; mt++)
#pragma unroll
        for (int nt = 0; nt < 4; nt++)
#pragma unroll
            for (int r = 0; r < 4; r++) acc[mt][nt][r] = 0.f;

    // prefetch demod scales now; consumed only in the epilogue
    const int row0 = lane >> 2;
    float dva[4], dvb[4];
#pragma unroll
    for (int mt = 0; mt < 4; mt++){
        dva[mt] = __ldg(&g_D[b*COUT + co0 + mt*16 + row0]);
        dvb[mt] = __ldg(&g_D[b*COUT + co0 + mt*16 + row0 + 8]);
    }

    const uint32_t aOff = (((lane & 15))*APAD + ((lane >> 4) << 3))*2;
    const int bg = lane >> 3;
    const uint32_t bOff = ((((bg & 1) << 3) + (lane & 7))*BPAD + wn*32 + ((bg >> 1) << 3))*2;

    auto load_chunk = [&](int ch, int buf){
        int sh  = ch >> 3;
        int ci0 = (ch & 7) << 6;
        int ky  = sh / 3;
        int kx  = sh - ky*3;
        const __half* aSrc = g_Ah + (size_t)co0*RED + (size_t)sh*CIN + ci0;
        const __half* xSrc = g_Xh + (((size_t)kx*Bsz + b)*CIN + ci0)*XPLANE
                           + (size_t)(y0 + ky)*XROW;
        uint32_t dA = s0 + buf*STAGE;
        uint32_t dB = dA + A_ST;
#pragma unroll
        for (int it = 0; it < 12; it++){
            int idx = tid + (it << 7);
            if (idx < 512){
                int m = idx >> 3, q = idx & 7;
                cp16(dA + m*(APAD*2) + q*16, aSrc + (size_t)m*RED + (q<<3));
            } else {
                int i2 = idx - 512;
                int k  = i2 >> 4;
                int q  = i2 & 15;
                cp16(dB + k*(BPAD*2) + q*16, xSrc + (size_t)k*XPLANE + (q<<3));
            }
        }
        asm volatile("cp.async.commit_group;");
    };

    load_chunk(0, 0);

    for (int c = 0; c < NCHUNK; c++){
        asm volatile("cp.async.wait_group 0;");
        __syncthreads();

        if (c + 1 < NCHUNK) load_chunk(c+1, (c+1) & 1);

        const uint32_t aBase = s0 + (c & 1)*STAGE;
        const uint32_t bBase = aBase + A_ST;
#pragma unroll
        for (int ks = 0; ks < 4; ks++){
            uint32_t afr[4][4], bfr[2][4];
#pragma unroll
            for (int mt = 0; mt < 4; mt++)
                ldsm_x4(afr[mt], aBase + aOff + (mt*16*APAD + ks*16)*2);
#pragma unroll
            for (int np = 0; np < 2; np++)
                ldsm_x4t(bfr[np], bBase + bOff + (ks*16*BPAD + np*16)*2);
#pragma unroll
            for (int mt = 0; mt < 4; mt++)
#pragma unroll
                for (int nt = 0; nt < 4; nt++)
                    mma_f16(acc[mt][nt], afr[mt], &bfr[nt>>1][(nt&1)*2]);
        }
    }

    // ---- epilogue ----
    const int col0 = (lane & 3) << 1;
#pragma unroll
    for (int mt = 0; mt < 4; mt++){
        int cout_a = co0 + mt*16 + row0;
        int cout_b = cout_a + 8;
        float* opa = out + ((size_t)(b*COUT + cout_a)*HH + y0)*WW;
        float* opb = out + ((size_t)(b*COUT + cout_b)*HH + y0)*WW;
#pragma unroll
        for (int nt = 0; nt < 4; nt++){
            int n  = wn*32 + nt*8 + col0;
            int yy = n >> 6;
            int xx = n & 63;
            float2 va, vb;
            va.x = acc[mt][nt][0]*dva[mt]; va.y = acc[mt][nt][1]*dva[mt];
            vb.x = acc[mt][nt][2]*dvb[mt]; vb.y = acc[mt][nt][3]*dvb[mt];
            *(float2*)(opa + (size_t)yy*WW + xx) = va;
            *(float2*)(opb + (size_t)yy*WW + xx) = vb;
        }
    }
}

// ---------------- launch --------------------------------------------------------
extern "C" void kernel_launch(void* const* d_in, const int* in_sizes, int n_in,
                              void* d_out, int out_size) {
    const float *x = nullptr, *style = nullptr, *weight = nullptr, *mod_w = nullptr;
    for (int i = 0; i < n_in; i++){
        switch (in_sizes[i]){
            case Bsz*CIN*HH*WW:   x      = (const float*)d_in[i]; break;
            case Bsz*CIN:         style  = (const float*)d_in[i]; break;
            case COUT*CIN*KAREA:  weight = (const float*)d_in[i]; break;
            case CIN*CIN:         mod_w  = (const float*)d_in[i]; break;
        }
    }
    float* out = (float*)d_out;

    cudaFuncSetAttribute(k_conv_mma, cudaFuncAttributeMaxDynamicSharedMemorySize, SMEM_SZ);

    k_style<<<(Bsz*CIN)/8, 256>>>(style, mod_w);
    k_prep<<<PREPO_BLKS + PREPX_BLKS, 256>>>(weight, x);

    dim3 grid(HH/2, COUT/64, Bsz);       // 32 x 8 x 8 = 2048 CTAs
    k_conv_mma<<<grid, 128, SMEM_SZ>>>(out);
}

// round 17
// speedup vs baseline: 1.1457x; 1.0121x over previous
#include <cuda_runtime.h>
#include <cuda_fp16.h>
#include <cstdint>
#include <math.h>

#define Bsz   8
#define CIN   512
#define COUT  512
#define HH    64
#define WW    64
#define KAREA 9
#define RED   (CIN*KAREA)

#define BK      64
#define NCHUNK  (KAREA*(CIN/BK))   // 72
#define XPAD_H  66
#define XROW    64
#define XPLANE  (XPAD_H*XROW)      // 4224

// ---------------- static device scratch --------------------------------------
__device__ float  g_S[Bsz*CIN];
__device__ float  g_S2[Bsz*CIN];
__device__ float  g_D[Bsz*COUT];
__device__ __half g_Ah[(size_t)COUT*KAREA*CIN];        // [o][k][i]
__device__ __half g_Xh[(size_t)3*Bsz*CIN*XPLANE];      // [kx][b][ci][y+1][x], pads stay 0

// ---------------- helpers ------------------------------------------------------
__device__ __forceinline__ uint32_t smem_u32(const void* p){
    uint32_t a;
    asm("{ .reg .u64 t; cvta.to.shared.u64 t, %1; cvt.u32.u64 %0, t; }" : "=r"(a) : "l"(p));
    return a;
}
__device__ __forceinline__ void cp16(uint32_t dst, const void* src){
    asm volatile("cp.async.cg.shared.global [%0], [%1], 16;" :: "r"(dst), "l"(src));
}
__device__ __forceinline__ void ldsm_x4(uint32_t* r, uint32_t addr){
    asm volatile("ldmatrix.sync.aligned.m8n8.x4.shared.b16 {%0,%1,%2,%3}, [%4];"
                 : "=r"(r[0]),"=r"(r[1]),"=r"(r[2]),"=r"(r[3]) : "r"(addr));
}
__device__ __forceinline__ void ldsm_x4t(uint32_t* r, uint32_t addr){
    asm volatile("ldmatrix.sync.aligned.m8n8.x4.trans.shared.b16 {%0,%1,%2,%3}, [%4];"
                 : "=r"(r[0]),"=r"(r[1]),"=r"(r[2]),"=r"(r[3]) : "r"(addr));
}
__device__ __forceinline__ void mma_f16(float* c, const uint32_t* a, const uint32_t* b){
    asm volatile("mma.sync.aligned.m16n8k16.row.col.f32.f16.f16.f32 "
        "{%0,%1,%2,%3}, {%4,%5,%6,%7}, {%8,%9}, {%0,%1,%2,%3};"
        : "+f"(c[0]),"+f"(c[1]),"+f"(c[2]),"+f"(c[3])
        : "r"(a[0]),"r"(a[1]),"r"(a[2]),"r"(a[3]), "r"(b[0]),"r"(b[1]));
}
__device__ __forceinline__ uint32_t h2pack(__half a, __half b){
    __half2 t = __halves2half2(a, b);
    return *(uint32_t*)&t;
}

// ---------------- prep 1: style modulation (warp per output) -------------------
__global__ void k_style(const float* __restrict__ style, const float* __restrict__ mw){
    int gw   = blockIdx.x*8 + (threadIdx.x >> 5);
    int lane = threadIdx.x & 31;
    int b = gw >> 9;
    int i = gw & 511;
    const float4* row = (const float4*)(mw + (size_t)i*CIN) + lane;
    const float4* st  = (const float4*)(style + (size_t)b*CIN) + lane;
    float acc = 0.f;
#pragma unroll
    for (int j = 0; j < 4; j++){
        float4 r = row[j*32];
        float4 s = st[j*32];
        acc += r.x*s.x + r.y*s.y + r.z*s.z + r.w*s.w;
    }
#pragma unroll
    for (int off = 16; off; off >>= 1) acc += __shfl_xor_sync(~0u, acc, off);
    if (!lane){ g_S[gw] = acc; g_S2[gw] = acc*acc; }
}

// ---------------- prep 2: FUSED (weight pack + demod) | (x expand) -------------
#define PREPO_BLKS COUT                            // 512
#define PREPX_BLKS ((Bsz*CIN*HH*WW)/(8*256))       // 8192

__global__ void __launch_bounds__(256)
k_prep(const float* __restrict__ w, const float* __restrict__ x){
    const int tid = threadIdx.x;
    if (blockIdx.x < PREPO_BLKS){
        // ---- per-cout weight pack + fused demod ----
        __shared__ float smw[RED];
        __shared__ float q[CIN];
        const int o = blockIdx.x;
        const float4* src = (const float4*)(w + (size_t)o*RED);
#pragma unroll
        for (int it = 0; it < RED/4/256 + 1; it++){
            int idx = tid + it*256;
            if (idx < RED/4) ((float4*)smw)[idx] = src[idx];
        }
        __syncthreads();
        __half* dst = g_Ah + (size_t)o*RED;
#pragma unroll
        for (int it = 0; it < RED/256; it++){
            int idx = tid + it*256;
            int k = idx >> 9;
            int i = idx & 511;
            dst[idx] = __float2half_rn(smw[i*KAREA + k]);
        }
#pragma unroll
        for (int it = 0; it < 2; it++){
            int i = tid + it*256;
            float s = 0.f;
#pragma unroll
            for (int k = 0; k < KAREA; k++){ float v = smw[i*KAREA + k]; s += v*v; }
            q[i] = s;
        }
        __syncthreads();
        int wb   = tid >> 5;
        int lane = tid & 31;
        const float* s2 = g_S2 + wb*CIN;
        float sum = 0.f;
#pragma unroll
        for (int j = 0; j < 16; j++){
            int i = lane + j*32;
            sum += q[i]*s2[i];
        }
#pragma unroll
        for (int off = 16; off; off >>= 1) sum += __shfl_xor_sync(~0u, sum, off);
        if (!lane)
            g_D[wb*COUT + o] = rsqrtf((float)RED) * rsqrtf(sum/(float)RED + 1e-8f);
    } else {
        // ---- x modulate + shift-expand (8 px/thread, aligned uint4 stores) ----
        int gid = (blockIdx.x - PREPO_BLKS)*256 + tid;
        int t  = gid & 7;
        int y  = (gid >> 3) & 63;
        int ci = (gid >> 9) & 511;
        int b  = gid >> 18;
        float s = g_S[b*CIN + ci];
        const float4* src = (const float4*)(x + (((size_t)(b*CIN + ci)*64 + y)<<6) + (t<<3));
        float4 f0 = src[0], f1 = src[1];
        float v0=f0.x*s, v1=f0.y*s, v2=f0.z*s, v3=f0.w*s;
        float v4=f1.x*s, v5=f1.y*s, v6=f1.z*s, v7=f1.w*s;
        __half h0=__float2half_rn(v0), h1=__float2half_rn(v1),
               h2=__float2half_rn(v2), h3=__float2half_rn(v3),
               h4=__float2half_rn(v4), h5=__float2half_rn(v5),
               h6=__float2half_rn(v6), h7=__float2half_rn(v7);
        float pl = __shfl_up_sync(~0u,  v7, 1);
        float nf = __shfl_down_sync(~0u, v0, 1);
        __half hpl = (t==0) ? __float2half_rn(0.f) : __float2half_rn(pl);
        __half hnf = (t==7) ? __float2half_rn(0.f) : __float2half_rn(nf);
        size_t rowOff = (size_t)(b*CIN + ci)*XPLANE + (size_t)(y+1)*XROW + (t<<3);
        const size_t kxStride = (size_t)Bsz*CIN*XPLANE;
        uint4 c1 = { h2pack(h0,h1), h2pack(h2,h3), h2pack(h4,h5), h2pack(h6,h7) };
        uint4 c0 = { h2pack(hpl,h0), h2pack(h1,h2), h2pack(h3,h4), h2pack(h5,h6) };
        uint4 c2 = { h2pack(h1,h2), h2pack(h3,h4), h2pack(h5,h6), h2pack(h7,hnf) };
        *(uint4*)(g_Xh + rowOff)              = c0;
        *(uint4*)(g_Xh + kxStride + rowOff)   = c1;
        *(uint4*)(g_Xh + 2*kxStride + rowOff) = c2;
    }
}

// ---------------- main mma.sync kernel ------------------------------------------
// CTA 64 couts x 128 px, 128 threads (4 warps, 1m x 4n), warp tile 64x32.
// BK=64, 2-stage cp.async, 4 CTAs/SM. At the measured HMMA/smem-crossbar floor.

#define APAD   72                    // halfs per A smem row (144B)
#define BPAD   136                   // halfs per B smem row (272B)
#define A_ST   (64*APAD*2)           // 9216 B
#define B_ST   (BK*BPAD*2)           // 17408 B
#define STAGE  (A_ST + B_ST)         // 26624 B
#define SMEM_SZ (2*STAGE)            // 53248 B

__global__ void __launch_bounds__(128, 4)
k_conv_mma(float* __restrict__ out)
{
    extern __shared__ __align__(16) char smraw[];
    const uint32_t s0 = smem_u32(smraw);

    const int tid  = threadIdx.x;
    const int lane = tid & 31;
    const int wn   = tid >> 5;

    const int b   = blockIdx.z;
    const int co0 = blockIdx.y << 6;
    const int y0  = blockIdx.x << 1;

    float acc[4][4][4];
#pragma unroll
    for (int mt = 0; mt < 4; mt++)
#pragma unroll
        for (int nt = 0; nt < 4; nt++)
#pragma unroll
            for (int r = 0; r < 4; r++) acc[mt][nt][r] = 0.f;

    const uint32_t aOff = (((lane & 15))*APAD + ((lane >> 4) << 3))*2;
    const int bg = lane >> 3;
    const uint32_t bOff = ((((bg & 1) << 3) + (lane & 7))*BPAD + wn*32 + ((bg >> 1) << 3))*2;

    auto load_chunk = [&](int ch, int buf){
        int sh  = ch >> 3;
        int ci0 = (ch & 7) << 6;
        int ky  = sh / 3;
        int kx  = sh - ky*3;
        const __half* aSrc = g_Ah + (size_t)co0*RED + (size_t)sh*CIN + ci0;
        const __half* xSrc = g_Xh + (((size_t)kx*Bsz + b)*CIN + ci0)*XPLANE
                           + (size_t)(y0 + ky)*XROW;
        uint32_t dA = s0 + buf*STAGE;
        uint32_t dB = dA + A_ST;
#pragma unroll
        for (int it = 0; it < 12; it++){
            int idx = tid + (it << 7);
            if (idx < 512){
                int m = idx >> 3, q = idx & 7;
                cp16(dA + m*(APAD*2) + q*16, aSrc + (size_t)m*RED + (q<<3));
            } else {
                int i2 = idx - 512;
                int k  = i2 >> 4;
                int q  = i2 & 15;
                cp16(dB + k*(BPAD*2) + q*16, xSrc + (size_t)k*XPLANE + (q<<3));
            }
        }
        asm volatile("cp.async.commit_group;");
    };

    load_chunk(0, 0);

    for (int c = 0; c < NCHUNK; c++){
        asm volatile("cp.async.wait_group 0;");
        __syncthreads();

        if (c + 1 < NCHUNK) load_chunk(c+1, (c+1) & 1);

        const uint32_t aBase = s0 + (c & 1)*STAGE;
        const uint32_t bBase = aBase + A_ST;
#pragma unroll
        for (int ks = 0; ks < 4; ks++){
            uint32_t afr[4][4], bfr[2][4];
#pragma unroll
            for (int mt = 0; mt < 4; mt++)
                ldsm_x4(afr[mt], aBase + aOff + (mt*16*APAD + ks*16)*2);
#pragma unroll
            for (int np = 0; np < 2; np++)
                ldsm_x4t(bfr[np], bBase + bOff + (ks*16*BPAD + np*16)*2);
#pragma unroll
            for (int mt = 0; mt < 4; mt++)
#pragma unroll
                for (int nt = 0; nt < 4; nt++)
                    mma_f16(acc[mt][nt], afr[mt], &bfr[nt>>1][(nt&1)*2]);
        }
    }

    // ---- epilogue ----
    const int row0 = lane >> 2;
    const int col0 = (lane & 3) << 1;
#pragma unroll
    for (int mt = 0; mt < 4; mt++){
        int cout_a = co0 + mt*16 + row0;
        int cout_b = cout_a + 8;
        float dva = g_D[b*COUT + cout_a];
        float dvb = g_D[b*COUT + cout_b];
        float* opa = out + ((size_t)(b*COUT + cout_a)*HH + y0)*WW;
        float* opb = out + ((size_t)(b*COUT + cout_b)*HH + y0)*WW;
#pragma unroll
        for (int nt = 0; nt < 4; nt++){
            int n  = wn*32 + nt*8 + col0;
            int yy = n >> 6;
            int xx = n & 63;
            float2 va, vb;
            va.x = acc[mt][nt][0]*dva; va.y = acc[mt][nt][1]*dva;
            vb.x = acc[mt][nt][2]*dvb; vb.y = acc[mt][nt][3]*dvb;
            *(float2*)(opa + (size_t)yy*WW + xx) = va;
            *(float2*)(opb + (size_t)yy*WW + xx) = vb;
        }
    }
}

// ---------------- launch --------------------------------------------------------
extern "C" void kernel_launch(void* const* d_in, const int* in_sizes, int n_in,
                              void* d_out, int out_size) {
    const float *x = nullptr, *style = nullptr, *weight = nullptr, *mod_w = nullptr;
    for (int i = 0; i < n_in; i++){
        switch (in_sizes[i]){
            case Bsz*CIN*HH*WW:   x      = (const float*)d_in[i]; break;
            case Bsz*CIN:         style  = (const float*)d_in[i]; break;
            case COUT*CIN*KAREA:  weight = (const float*)d_in[i]; break;
            case CIN*CIN:         mod_w  = (const float*)d_in[i]; break;
        }
    }
    float* out = (float*)d_out;

    cudaFuncSetAttribute(k_conv_mma, cudaFuncAttributeMaxDynamicSharedMemorySize, SMEM_SZ);

    k_style<<<(Bsz*CIN)/8, 256>>>(style, mod_w);
    k_prep<<<PREPO_BLKS + PREPX_BLKS, 256>>>(weight, x);

    dim3 grid(HH/2, COUT/64, Bsz);       // 32 x 8 x 8 = 2048 CTAs
    k_conv_mma<<<grid, 128, SMEM_SZ>>>(out);
}